// round 11
// baseline (speedup 1.0000x reference)
#include <cuda_runtime.h>
#include <cuda_fp16.h>
#include <cstdint>

constexpr int S  = 24;
constexpr int Bn = 256;
constexpr int Dm = 1024;
constexpr int Ln = 12;
constexpr int Vn = 32000;
constexpr int DH = 64;
constexpr int Mr = S * Bn;          // 6144
constexpr int QKVN = 3 * Dm;        // 3072
constexpr int WROWS = Ln * QKVN;    // 36864
constexpr size_t MD = (size_t)16 * 256 * 24 * 64;   // elems per q/k/v plane

constexpr int BM = 128, BN = 128, BK = 64, STAGES = 3;
constexpr int STAGE_BYTES = (BM * BK + BN * BK) * 2;      // 32 KB
constexpr int SMEM_BYTES  = STAGES * STAGE_BYTES;         // 96 KB

// ---------------- scratch (device globals; no allocation) ----------------
__device__ float g_x[(size_t)Mr * Dm];
__device__ float g_qkv[3 * MD];                // [mat][h][b][s][d]
__device__ uint16_t g_xh16[(size_t)Mr * Dm];   // fp16 x
__device__ uint16_t g_w16[(size_t)WROWS * Dm]; // fp16 qkv weights
__device__ uint16_t g_ow16[(size_t)Vn * Dm];   // fp16 out_w

__device__ __forceinline__ uint32_t smem_u32(const void* p) {
    uint32_t a;
    asm("{ .reg .u64 t; cvta.to.shared.u64 t, %1; cvt.u32.u64 %0, t; }" : "=r"(a) : "l"(p));
    return a;
}

// xor swizzle for 128-byte rows (BK=64 b16): 16B chunk index xored with row%8
__device__ __forceinline__ uint32_t swz(int row, int g) {
    return (uint32_t)(row * 128 + ((g ^ (row & 7)) << 4));
}

// ---------------------------------------------------------------------------
// fp16 GEMM via mma.sync: C[128,128] = A[128,1024] . W[128,1024]^T + bias
// QKVMAP=false: row-major C.  QKVMAP=true: scatter into [mat][h][b][s][d].
// 256 threads, 8 warps (4m x 2n), warp tile 32x64, cp.async 3-stage.
// A-fragments double-buffered across the 4 k16-steps.
// ---------------------------------------------------------------------------
template<bool QKVMAP>
__device__ __forceinline__ void gemm_core(
    const uint16_t* __restrict__ A, const uint16_t* __restrict__ W,
    const float* __restrict__ bias, float* __restrict__ C, int ldC,
    int mT, int nT)
{
    constexpr int NIT_ = 16;
    extern __shared__ char smem[];
    const uint32_t sb = smem_u32(smem);
    const int tid = threadIdx.x;
    const int lane = tid & 31;
    const int wid = tid >> 5;
    const int wm = wid & 3;         // warp m index -> rows 32*wm
    const int wn = wid >> 2;        // warp n index -> cols 64*wn

    auto loadStage = [&](int it, int slot) {
        const int k0 = it * BK;
        const uint32_t sa = sb + slot * STAGE_BYTES;
        const uint32_t sw = sa + BM * BK * 2;
#pragma unroll
        for (int i = 0; i < 4; i++) {
            int ch = tid + i * 256;
            int r = ch >> 3, cb = ch & 7;
            const void* gp = A + (size_t)r * Dm + k0 + cb * 8;
            asm volatile("cp.async.cg.shared.global [%0], [%1], 16;"
                         :: "r"(sa + swz(r, cb)), "l"(gp));
        }
#pragma unroll
        for (int i = 0; i < 4; i++) {
            int ch = tid + i * 256;
            int r = ch >> 3, cb = ch & 7;
            const void* gp = W + (size_t)r * Dm + k0 + cb * 8;
            asm volatile("cp.async.cg.shared.global [%0], [%1], 16;"
                         :: "r"(sw + swz(r, cb)), "l"(gp));
        }
        asm volatile("cp.async.commit_group;");
    };

    float acc[2][8][4];
#pragma unroll
    for (int a = 0; a < 2; a++)
#pragma unroll
        for (int b = 0; b < 8; b++)
#pragma unroll
            for (int c = 0; c < 4; c++) acc[a][b][c] = 0.f;

    loadStage(0, 0);
    loadStage(1, 1);

    for (int it = 0; it < NIT_; it++) {
        if (it + 2 < NIT_) asm volatile("cp.async.wait_group 1;");
        else               asm volatile("cp.async.wait_group 0;");
        __syncthreads();
        if (it + 2 < NIT_) loadStage(it + 2, (it + 2) % STAGES);

        const uint32_t sa = sb + (it % STAGES) * STAGE_BYTES;
        const uint32_t sw = sa + BM * BK * 2;

        uint32_t afr[2][2][4];       // [buf][mi][4]
        auto loadA = [&](int q, int buf) {
#pragma unroll
            for (int mi = 0; mi < 2; mi++) {
                int m = wm * 32 + mi * 16 + (lane & 15);
                int g = 2 * q + (lane >> 4);
                asm volatile("ldmatrix.sync.aligned.m8n8.x4.shared.b16 {%0,%1,%2,%3}, [%4];"
                             : "=r"(afr[buf][mi][0]), "=r"(afr[buf][mi][1]),
                               "=r"(afr[buf][mi][2]), "=r"(afr[buf][mi][3])
                             : "r"(sa + swz(m, g)));
            }
        };
        loadA(0, 0);
#pragma unroll
        for (int q = 0; q < 4; q++) {           // k16 steps within BK=64
            const int cur = q & 1;
            if (q < 3) loadA(q + 1, cur ^ 1);
            uint32_t bfr[8][2];
#pragma unroll
            for (int nj = 0; nj < 8; nj += 2) {
                int n = wn * 64 + nj * 8 + (lane & 7) + ((lane & 16) >> 1);
                int g = 2 * q + ((lane >> 3) & 1);
                asm volatile("ldmatrix.sync.aligned.m8n8.x4.shared.b16 {%0,%1,%2,%3}, [%4];"
                             : "=r"(bfr[nj][0]), "=r"(bfr[nj][1]),
                               "=r"(bfr[nj + 1][0]), "=r"(bfr[nj + 1][1])
                             : "r"(sw + swz(n, g)));
            }
#pragma unroll
            for (int mi = 0; mi < 2; mi++)
#pragma unroll
                for (int nj = 0; nj < 8; nj++) {
                    asm volatile(
                        "mma.sync.aligned.m16n8k16.row.col.f32.f16.f16.f32 "
                        "{%0,%1,%2,%3}, {%4,%5,%6,%7}, {%8,%9}, {%0,%1,%2,%3};"
                        : "+f"(acc[mi][nj][0]), "+f"(acc[mi][nj][1]),
                          "+f"(acc[mi][nj][2]), "+f"(acc[mi][nj][3])
                        : "r"(afr[cur][mi][0]), "r"(afr[cur][mi][1]),
                          "r"(afr[cur][mi][2]), "r"(afr[cur][mi][3]),
                          "r"(bfr[nj][0]), "r"(bfr[nj][1]));
                }
        }
    }

    // epilogue
    const int r0 = wm * 32 + (lane >> 2);
    const int cl = 2 * (lane & 3);
#pragma unroll
    for (int mi = 0; mi < 2; mi++)
#pragma unroll
        for (int ro = 0; ro < 2; ro++) {
            int rg = mT * 128 + r0 + mi * 16 + ro * 8;     // global row (s*256+b)
#pragma unroll
            for (int nj = 0; nj < 8; nj++) {
                int colL = wn * 64 + nj * 8 + cl;
                float2 o;
                o.x = acc[mi][nj][ro * 2 + 0] + bias[colL];
                o.y = acc[mi][nj][ro * 2 + 1] + bias[colL + 1];
                if (QKVMAP) {
                    int cg  = nT * 128 + colL;
                    int mat = cg >> 10;
                    int hh  = (cg >> 6) & 15;
                    int dd  = cg & 63;
                    int s   = rg >> 8;
                    int bb  = rg & 255;
                    float* dst = C + (size_t)mat * MD
                                 + (size_t)((((hh << 8) + bb) * 24 + s) << 6) + dd;
                    *reinterpret_cast<float2*>(dst) = o;
                } else {
                    *reinterpret_cast<float2*>(
                        C + (size_t)rg * ldC + nT * 128 + colL) = o;
                }
            }
        }
}

// QKV projection: grid (48, 24)
__global__ void __launch_bounds__(256, 2) gemm_qkv_tc(
    int layer, const float* __restrict__ qb, const float* __restrict__ kb,
    const float* __restrict__ vb)
{
    const int mT = blockIdx.x, nT = blockIdx.y;
    const size_t aOff = (size_t)mT * 128 * Dm;
    const size_t wOff = (size_t)(layer * QKVN + nT * 128) * Dm;
    const int mat = nT >> 3;
    const float* bias = ((mat == 0) ? qb : (mat == 1) ? kb : vb)
                        + (size_t)layer * Dm + (nT & 7) * 128;
    gemm_core<true>(g_xh16 + aOff, g_w16 + wOff, bias, g_qkv, 0, mT, nT);
}

// Final logits: grid (48, 250)
__global__ void __launch_bounds__(256, 2) gemm_out_tc(
    const float* __restrict__ ob, float* __restrict__ out)
{
    const int mT = blockIdx.x, nT = blockIdx.y;
    const size_t aOff = (size_t)mT * 128 * Dm;
    const size_t wOff = (size_t)nT * 128 * Dm;
    gemm_core<false>(g_xh16 + aOff, g_ow16 + wOff, ob + nT * 128, out, Vn, mT, nT);
}

// ---------------------------------------------------------------------------
// Weight prep: fp32 -> fp16
// ---------------------------------------------------------------------------
__global__ void conv_wqkv16(const float* __restrict__ qw, const float* __restrict__ kw,
                            const float* __restrict__ vw) {
    size_t t = (size_t)blockIdx.x * 256 + threadIdx.x;
    size_t e = t * 4;
    int row = (int)(e >> 10);
    int col = (int)(e & 1023);
    int l   = row / 3072;
    int rem = row - l * 3072;
    int mat = rem >> 10;
    int n   = rem & 1023;
    const float* src = ((mat == 0) ? qw : (mat == 1) ? kw : vw)
                       + (((size_t)l * 1024 + n) << 10) + col;
    float4 v = *reinterpret_cast<const float4*>(src);
    size_t d = ((size_t)row << 10) + col;
    *reinterpret_cast<__half2*>(g_w16 + d)     = __floats2half2_rn(v.x, v.y);
    *reinterpret_cast<__half2*>(g_w16 + d + 2) = __floats2half2_rn(v.z, v.w);
}

__global__ void conv_wout16(const float* __restrict__ ow) {
    size_t e = ((size_t)blockIdx.x * 256 + threadIdx.x) * 4;   // < Vn*Dm
    float4 v = *reinterpret_cast<const float4*>(ow + e);
    *reinterpret_cast<__half2*>(g_ow16 + e)     = __floats2half2_rn(v.x, v.y);
    *reinterpret_cast<__half2*>(g_ow16 + e + 2) = __floats2half2_rn(v.z, v.w);
}

// ---------------------------------------------------------------------------
// Embedding + fp16 convert
// ---------------------------------------------------------------------------
__global__ void embed_kernel(const int* __restrict__ inputs,
                             const float* __restrict__ tok,
                             const float* __restrict__ pe) {
    int row = blockIdx.x;          // s*B + b
    int s = row / Bn;
    int t = inputs[row];
    const float4* te = reinterpret_cast<const float4*>(tok + (size_t)t * Dm);
    const float4* pp = reinterpret_cast<const float4*>(pe + (size_t)s * Dm);
    float4 a = te[threadIdx.x];
    float4 b = pp[threadIdx.x];
    float4 o = make_float4(a.x + b.x, a.y + b.y, a.z + b.z, a.w + b.w);
    size_t d = (size_t)row * Dm + threadIdx.x * 4;
    *reinterpret_cast<float4*>(g_x + d) = o;
    *reinterpret_cast<__half2*>(g_xh16 + d)     = __floats2half2_rn(o.x, o.y);
    *reinterpret_cast<__half2*>(g_xh16 + d + 2) = __floats2half2_rn(o.z, o.w);
}

// ---------------------------------------------------------------------------
// Attention per (h,b): register-blocked scores (2x2), warp softmax,
// float4-blocked AV + vectorized residual.  blockIdx.x = h*256 + b.
// ---------------------------------------------------------------------------
constexpr int LDA = 68;   // smem row stride (floats): 272B, 16B-aligned

__global__ void __launch_bounds__(256) attn_kernel() {
    int bh = blockIdx.x;
    int b = bh & 255;
    int h = bh >> 8;
    __shared__ float qs[S][LDA];
    __shared__ float ks[S][LDA];
    __shared__ float vs[S][LDA];
    __shared__ float sc[S][S];
    int tid = threadIdx.x;
    int lane = tid & 31;
    int w = tid >> 5;

    const float* qp = g_qkv + (size_t)(((h << 8) + b) * 24) * 64;   // 1536 floats
    const float* kp = qp + MD;
    const float* vp = qp + 2 * MD;
    for (int p = tid; p < S * DH / 4; p += 256) {     // 384 float4 per matrix
        int s = p >> 4, d4 = (p & 15) * 4;
        *reinterpret_cast<float4*>(&qs[s][d4]) = reinterpret_cast<const float4*>(qp)[p];
        *reinterpret_cast<float4*>(&ks[s][d4]) = reinterpret_cast<const float4*>(kp)[p];
        *reinterpret_cast<float4*>(&vs[s][d4]) = reinterpret_cast<const float4*>(vp)[p];
    }
    __syncthreads();

    constexpr float scale = 0.03125f;   // 1/sqrt(1024)
    // scores: 2x2 register blocking, 144 active threads (12x12 blocks)
    if (tid < 144) {
        int si0 = (tid / 12) * 2, ti0 = (tid % 12) * 2;
        float a00 = 0.f, a01 = 0.f, a10 = 0.f, a11 = 0.f;
#pragma unroll
        for (int d4 = 0; d4 < DH; d4 += 4) {
            float4 q0 = *reinterpret_cast<const float4*>(&qs[si0][d4]);
            float4 q1 = *reinterpret_cast<const float4*>(&qs[si0 + 1][d4]);
            float4 k0 = *reinterpret_cast<const float4*>(&ks[ti0][d4]);
            float4 k1 = *reinterpret_cast<const float4*>(&ks[ti0 + 1][d4]);
            a00 = fmaf(q0.x, k0.x, fmaf(q0.y, k0.y, fmaf(q0.z, k0.z, fmaf(q0.w, k0.w, a00))));
            a01 = fmaf(q0.x, k1.x, fmaf(q0.y, k1.y, fmaf(q0.z, k1.z, fmaf(q0.w, k1.w, a01))));
            a10 = fmaf(q1.x, k0.x, fmaf(q1.y, k0.y, fmaf(q1.z, k0.z, fmaf(q1.w, k0.w, a10))));
            a11 = fmaf(q1.x, k1.x, fmaf(q1.y, k1.y, fmaf(q1.z, k1.z, fmaf(q1.w, k1.w, a11))));
        }
        sc[si0][ti0]         = a00 * scale;
        sc[si0][ti0 + 1]     = a01 * scale;
        sc[si0 + 1][ti0]     = a10 * scale;
        sc[si0 + 1][ti0 + 1] = a11 * scale;
    }
    __syncthreads();

    // warp-parallel softmax: warp w handles rows w, w+8, w+16
    for (int r = w; r < S; r += 8) {
        float v = (lane < S) ? sc[r][lane] : -1e30f;
        float mx = v;
#pragma unroll
        for (int o = 16; o; o >>= 1) mx = fmaxf(mx, __shfl_xor_sync(0xFFFFFFFFu, mx, o));
        float e = (lane < S) ? expf(v - mx) : 0.f;
        float sum = e;
#pragma unroll
        for (int o = 16; o; o >>= 1) sum += __shfl_xor_sync(0xFFFFFFFFu, sum, o);
        if (lane < S) sc[r][lane] = e * (1.f / sum);
    }
    __syncthreads();

    // AV + residual, float4-blocked: item = (s, group of 4 d)
    for (int p = tid; p < S * (DH / 4); p += 256) {    // 384 items
        int s = p >> 4, d4 = (p & 15) * 4;
        float4 o = make_float4(0.f, 0.f, 0.f, 0.f);
#pragma unroll
        for (int t = 0; t < S; t++) {
            float wgt = sc[s][t];
            float4 v = *reinterpret_cast<const float4*>(&vs[t][d4]);
            o.x = fmaf(wgt, v.x, o.x);
            o.y = fmaf(wgt, v.y, o.y);
            o.z = fmaf(wgt, v.z, o.z);
            o.w = fmaf(wgt, v.w, o.w);
        }
        size_t xi = (size_t)(s * Bn + b) * Dm + h * DH + d4;
        float4 xv = *reinterpret_cast<const float4*>(g_x + xi);
        xv.x += o.x; xv.y += o.y; xv.z += o.z; xv.w += o.w;
        *reinterpret_cast<float4*>(g_x + xi) = xv;
        *reinterpret_cast<__half2*>(g_xh16 + xi)     = __floats2half2_rn(xv.x, xv.y);
        *reinterpret_cast<__half2*>(g_xh16 + xi + 2) = __floats2half2_rn(xv.z, xv.w);
    }
}

// ---------------------------------------------------------------------------
extern "C" void kernel_launch(void* const* d_in, const int* in_sizes, int n_in,
                              void* d_out, int out_size) {
    const int*   inputs = (const int*)d_in[0];
    // d_in[1] = mask (reference drops it)
    const float* tok = (const float*)d_in[2];
    const float* pe  = (const float*)d_in[3];
    const float* qw  = (const float*)d_in[4];
    const float* qb  = (const float*)d_in[5];
    const float* kw  = (const float*)d_in[6];
    const float* kb  = (const float*)d_in[7];
    const float* vw  = (const float*)d_in[8];
    const float* vb  = (const float*)d_in[9];
    const float* ow  = (const float*)d_in[10];
    const float* ob  = (const float*)d_in[11];
    float* out = (float*)d_out;

    cudaFuncSetAttribute(gemm_qkv_tc, cudaFuncAttributeMaxDynamicSharedMemorySize, SMEM_BYTES);
    cudaFuncSetAttribute(gemm_out_tc, cudaFuncAttributeMaxDynamicSharedMemorySize, SMEM_BYTES);

    conv_wqkv16<<<WROWS, 256>>>(qw, kw, vw);
    conv_wout16<<<Vn, 256>>>(ow);
    embed_kernel<<<Mr, 256>>>(inputs, tok, pe);

    for (int l = 0; l < Ln; l++) {
        gemm_qkv_tc<<<dim3(48, 24), 256, SMEM_BYTES>>>(l, qb, kb, vb);
        attn_kernel<<<Bn * 16, 256>>>();
    }
    gemm_out_tc<<<dim3(48, 250), 256, SMEM_BYTES>>>(ob, out);
}

// round 12
// speedup vs baseline: 1.0347x; 1.0347x over previous
#include <cuda_runtime.h>
#include <cuda_fp16.h>
#include <cstdint>

constexpr int S  = 24;
constexpr int Bn = 256;
constexpr int Dm = 1024;
constexpr int Ln = 12;
constexpr int Vn = 32000;
constexpr int DH = 64;
constexpr int Mr = S * Bn;          // 6144
constexpr int QKVN = 3 * Dm;        // 3072
constexpr int WROWS = Ln * QKVN;    // 36864
constexpr size_t MD = (size_t)16 * 256 * 24 * 64;   // elems per plane

constexpr int BM = 128, BN = 128, BK = 64, STAGES = 3;
constexpr int STAGE_BYTES = (BM * BK + BN * BK) * 2;      // 32 KB
constexpr int SMEM_BYTES  = STAGES * STAGE_BYTES;         // 96 KB

// ---------------- scratch (device globals; no allocation) ----------------
__device__ float g_x[(size_t)Mr * Dm];
__device__ float g_v[MD];                      // fp32 v   [h][b][s][d]
__device__ uint16_t g_qk16[2 * MD];            // fp16 q,k [m][h][b][s][d]
__device__ uint16_t g_xh16[(size_t)Mr * Dm];   // fp16 x
__device__ uint16_t g_w16[(size_t)WROWS * Dm]; // fp16 qkv weights
__device__ uint16_t g_ow16[(size_t)Vn * Dm];   // fp16 out_w

__device__ __forceinline__ uint32_t smem_u32(const void* p) {
    uint32_t a;
    asm("{ .reg .u64 t; cvta.to.shared.u64 t, %1; cvt.u32.u64 %0, t; }" : "=r"(a) : "l"(p));
    return a;
}

// xor swizzle for 128-byte rows (BK=64 b16): 16B chunk index xored with row%8
__device__ __forceinline__ uint32_t swz(int row, int g) {
    return (uint32_t)(row * 128 + ((g ^ (row & 7)) << 4));
}

// ---------------------------------------------------------------------------
// fp16 GEMM via mma.sync: C[128,128] = A[128,1024] . W[128,1024]^T + bias
// QKVMAP=false: row-major fp32 C.  QKVMAP=true: q,k -> fp16 planes of g_qk16,
// v -> fp32 g_v, all in [h][b][s][d] attention layout.
// 256 threads, 8 warps (4m x 2n), warp tile 32x64, cp.async 3-stage.
// ---------------------------------------------------------------------------
template<bool QKVMAP>
__device__ __forceinline__ void gemm_core(
    const uint16_t* __restrict__ A, const uint16_t* __restrict__ W,
    const float* __restrict__ bias, float* __restrict__ C, int ldC,
    int mT, int nT)
{
    constexpr int NIT_ = 16;
    extern __shared__ char smem[];
    const uint32_t sb = smem_u32(smem);
    const int tid = threadIdx.x;
    const int lane = tid & 31;
    const int wid = tid >> 5;
    const int wm = wid & 3;         // warp m index -> rows 32*wm
    const int wn = wid >> 2;        // warp n index -> cols 64*wn

    auto loadStage = [&](int it, int slot) {
        const int k0 = it * BK;
        const uint32_t sa = sb + slot * STAGE_BYTES;
        const uint32_t sw = sa + BM * BK * 2;
#pragma unroll
        for (int i = 0; i < 4; i++) {
            int ch = tid + i * 256;
            int r = ch >> 3, cb = ch & 7;
            const void* gp = A + (size_t)r * Dm + k0 + cb * 8;
            asm volatile("cp.async.cg.shared.global [%0], [%1], 16;"
                         :: "r"(sa + swz(r, cb)), "l"(gp));
        }
#pragma unroll
        for (int i = 0; i < 4; i++) {
            int ch = tid + i * 256;
            int r = ch >> 3, cb = ch & 7;
            const void* gp = W + (size_t)r * Dm + k0 + cb * 8;
            asm volatile("cp.async.cg.shared.global [%0], [%1], 16;"
                         :: "r"(sw + swz(r, cb)), "l"(gp));
        }
        asm volatile("cp.async.commit_group;");
    };

    float acc[2][8][4];
#pragma unroll
    for (int a = 0; a < 2; a++)
#pragma unroll
        for (int b = 0; b < 8; b++)
#pragma unroll
            for (int c = 0; c < 4; c++) acc[a][b][c] = 0.f;

    loadStage(0, 0);
    loadStage(1, 1);

    for (int it = 0; it < NIT_; it++) {
        if (it + 2 < NIT_) asm volatile("cp.async.wait_group 1;");
        else               asm volatile("cp.async.wait_group 0;");
        __syncthreads();
        if (it + 2 < NIT_) loadStage(it + 2, (it + 2) % STAGES);

        const uint32_t sa = sb + (it % STAGES) * STAGE_BYTES;
        const uint32_t sw = sa + BM * BK * 2;
#pragma unroll
        for (int q = 0; q < 4; q++) {           // k16 steps within BK=64
            uint32_t afr[2][4], bfr[8][2];
#pragma unroll
            for (int mi = 0; mi < 2; mi++) {
                int m = wm * 32 + mi * 16 + (lane & 15);
                int g = 2 * q + (lane >> 4);
                asm volatile("ldmatrix.sync.aligned.m8n8.x4.shared.b16 {%0,%1,%2,%3}, [%4];"
                             : "=r"(afr[mi][0]), "=r"(afr[mi][1]),
                               "=r"(afr[mi][2]), "=r"(afr[mi][3])
                             : "r"(sa + swz(m, g)));
            }
#pragma unroll
            for (int nj = 0; nj < 8; nj += 2) {
                int n = wn * 64 + nj * 8 + (lane & 7) + ((lane & 16) >> 1);
                int g = 2 * q + ((lane >> 3) & 1);
                asm volatile("ldmatrix.sync.aligned.m8n8.x4.shared.b16 {%0,%1,%2,%3}, [%4];"
                             : "=r"(bfr[nj][0]), "=r"(bfr[nj][1]),
                               "=r"(bfr[nj + 1][0]), "=r"(bfr[nj + 1][1])
                             : "r"(sw + swz(n, g)));
            }
#pragma unroll
            for (int mi = 0; mi < 2; mi++)
#pragma unroll
                for (int nj = 0; nj < 8; nj++) {
                    asm volatile(
                        "mma.sync.aligned.m16n8k16.row.col.f32.f16.f16.f32 "
                        "{%0,%1,%2,%3}, {%4,%5,%6,%7}, {%8,%9}, {%0,%1,%2,%3};"
                        : "+f"(acc[mi][nj][0]), "+f"(acc[mi][nj][1]),
                          "+f"(acc[mi][nj][2]), "+f"(acc[mi][nj][3])
                        : "r"(afr[mi][0]), "r"(afr[mi][1]),
                          "r"(afr[mi][2]), "r"(afr[mi][3]),
                          "r"(bfr[nj][0]), "r"(bfr[nj][1]));
                }
        }
    }

    // epilogue
    const int r0 = wm * 32 + (lane >> 2);
    const int cl = 2 * (lane & 3);
#pragma unroll
    for (int mi = 0; mi < 2; mi++)
#pragma unroll
        for (int ro = 0; ro < 2; ro++) {
            int rg = mT * 128 + r0 + mi * 16 + ro * 8;     // global row (s*256+b)
#pragma unroll
            for (int nj = 0; nj < 8; nj++) {
                int colL = wn * 64 + nj * 8 + cl;
                float2 o;
                o.x = acc[mi][nj][ro * 2 + 0] + bias[colL];
                o.y = acc[mi][nj][ro * 2 + 1] + bias[colL + 1];
                if (QKVMAP) {
                    int cg  = nT * 128 + colL;
                    int mat = cg >> 10;                  // 0=q 1=k 2=v
                    int hh  = (cg >> 6) & 15;
                    int dd  = cg & 63;
                    int s   = rg >> 8;
                    int bb  = rg & 255;
                    size_t idx = (size_t)((((hh << 8) + bb) * 24 + s) << 6) + dd;
                    if (mat == 2) {
                        *reinterpret_cast<float2*>(g_v + idx) = o;
                    } else {
                        *reinterpret_cast<__half2*>(g_qk16 + (size_t)mat * MD + idx) =
                            __floats2half2_rn(o.x, o.y);
                    }
                } else {
                    *reinterpret_cast<float2*>(
                        C + (size_t)rg * ldC + nT * 128 + colL) = o;
                }
            }
        }
}

// QKV projection: grid (48, 24)
__global__ void __launch_bounds__(256, 2) gemm_qkv_tc(
    int layer, const float* __restrict__ qb, const float* __restrict__ kb,
    const float* __restrict__ vb)
{
    const int mT = blockIdx.x, nT = blockIdx.y;
    const size_t aOff = (size_t)mT * 128 * Dm;
    const size_t wOff = (size_t)(layer * QKVN + nT * 128) * Dm;
    const int mat = nT >> 3;
    const float* bias = ((mat == 0) ? qb : (mat == 1) ? kb : vb)
                        + (size_t)layer * Dm + (nT & 7) * 128;
    gemm_core<true>(g_xh16 + aOff, g_w16 + wOff, bias, nullptr, 0, mT, nT);
}

// Final logits: grid (48, 250)
__global__ void __launch_bounds__(256, 2) gemm_out_tc(
    const float* __restrict__ ob, float* __restrict__ out)
{
    const int mT = blockIdx.x, nT = blockIdx.y;
    const size_t aOff = (size_t)mT * 128 * Dm;
    const size_t wOff = (size_t)nT * 128 * Dm;
    gemm_core<false>(g_xh16 + aOff, g_ow16 + wOff, ob + nT * 128, out, Vn, mT, nT);
}

// ---------------------------------------------------------------------------
// Weight prep: fp32 -> fp16
// ---------------------------------------------------------------------------
__global__ void conv_wqkv16(const float* __restrict__ qw, const float* __restrict__ kw,
                            const float* __restrict__ vw) {
    size_t t = (size_t)blockIdx.x * 256 + threadIdx.x;
    size_t e = t * 4;
    int row = (int)(e >> 10);
    int col = (int)(e & 1023);
    int l   = row / 3072;
    int rem = row - l * 3072;
    int mat = rem >> 10;
    int n   = rem & 1023;
    const float* src = ((mat == 0) ? qw : (mat == 1) ? kw : vw)
                       + (((size_t)l * 1024 + n) << 10) + col;
    float4 v = *reinterpret_cast<const float4*>(src);
    size_t d = ((size_t)row << 10) + col;
    *reinterpret_cast<__half2*>(g_w16 + d)     = __floats2half2_rn(v.x, v.y);
    *reinterpret_cast<__half2*>(g_w16 + d + 2) = __floats2half2_rn(v.z, v.w);
}

__global__ void conv_wout16(const float* __restrict__ ow) {
    size_t e = ((size_t)blockIdx.x * 256 + threadIdx.x) * 4;   // < Vn*Dm
    float4 v = *reinterpret_cast<const float4*>(ow + e);
    *reinterpret_cast<__half2*>(g_ow16 + e)     = __floats2half2_rn(v.x, v.y);
    *reinterpret_cast<__half2*>(g_ow16 + e + 2) = __floats2half2_rn(v.z, v.w);
}

// ---------------------------------------------------------------------------
// Embedding + fp16 convert
// ---------------------------------------------------------------------------
__global__ void embed_kernel(const int* __restrict__ inputs,
                             const float* __restrict__ tok,
                             const float* __restrict__ pe) {
    int row = blockIdx.x;          // s*B + b
    int s = row / Bn;
    int t = inputs[row];
    const float4* te = reinterpret_cast<const float4*>(tok + (size_t)t * Dm);
    const float4* pp = reinterpret_cast<const float4*>(pe + (size_t)s * Dm);
    float4 a = te[threadIdx.x];
    float4 b = pp[threadIdx.x];
    float4 o = make_float4(a.x + b.x, a.y + b.y, a.z + b.z, a.w + b.w);
    size_t d = (size_t)row * Dm + threadIdx.x * 4;
    *reinterpret_cast<float4*>(g_x + d) = o;
    *reinterpret_cast<__half2*>(g_xh16 + d)     = __floats2half2_rn(o.x, o.y);
    *reinterpret_cast<__half2*>(g_xh16 + d + 2) = __floats2half2_rn(o.z, o.w);
}

// ---------------------------------------------------------------------------
// Attention per (h,b): fp16 q/k scores with q-sharing, warp softmax,
// fp32 float4 AV + vectorized residual.  blockIdx.x = h*256 + b.
// ---------------------------------------------------------------------------
constexpr int LDV = 68;   // v smem row stride (floats), 16B-aligned rows
constexpr int LDH = 33;   // q/k smem row stride (half2), odd -> conflict-free

__global__ void __launch_bounds__(256) attn_kernel() {
    int bh = blockIdx.x;
    int b = bh & 255;
    int h = bh >> 8;
    __shared__ __half2 qs2[S][LDH];
    __shared__ __half2 ks2[S][LDH];
    __shared__ float vs[S][LDV];
    __shared__ float sc[S][S];
    int tid = threadIdx.x;
    int lane = tid & 31;
    int w = tid >> 5;

    const size_t base = (size_t)(((h << 8) + b) * 24) * 64;
    // q,k: 1536 halves each = 192 uint4 each; v: 384 float4
    const uint4* qp = reinterpret_cast<const uint4*>(g_qk16 + base);
    const uint4* kp = reinterpret_cast<const uint4*>(g_qk16 + MD + base);
    const float4* vp = reinterpret_cast<const float4*>(g_v + base);
    for (int p = tid; p < 192; p += 256) {
        int s = p >> 3, c = (p & 7) * 4;     // 4 half2 per uint4
        uint4 qv = qp[p];
        uint4 kv = kp[p];
        qs2[s][c]     = *reinterpret_cast<__half2*>(&qv.x);
        qs2[s][c + 1] = *reinterpret_cast<__half2*>(&qv.y);
        qs2[s][c + 2] = *reinterpret_cast<__half2*>(&qv.z);
        qs2[s][c + 3] = *reinterpret_cast<__half2*>(&qv.w);
        ks2[s][c]     = *reinterpret_cast<__half2*>(&kv.x);
        ks2[s][c + 1] = *reinterpret_cast<__half2*>(&kv.y);
        ks2[s][c + 2] = *reinterpret_cast<__half2*>(&kv.z);
        ks2[s][c + 3] = *reinterpret_cast<__half2*>(&kv.w);
    }
    for (int p = tid; p < 384; p += 256) {
        int s = p >> 4, d4 = (p & 15) * 4;
        *reinterpret_cast<float4*>(&vs[s][d4]) = vp[p];
    }
    __syncthreads();

    constexpr float scale = 0.03125f;   // 1/sqrt(1024)
    // scores: thread handles (si,tj) and (si,tj+12); q loaded once
    for (int p = tid; p < 288; p += 256) {
        int si = p / 12, tj = p % 12;
        float a0 = 0.f, a1 = 0.f;
#pragma unroll
        for (int j = 0; j < 32; j++) {
            float2 q  = __half22float2(qs2[si][j]);
            float2 k0 = __half22float2(ks2[tj][j]);
            float2 k1 = __half22float2(ks2[tj + 12][j]);
            a0 = fmaf(q.x, k0.x, fmaf(q.y, k0.y, a0));
            a1 = fmaf(q.x, k1.x, fmaf(q.y, k1.y, a1));
        }
        sc[si][tj]      = a0 * scale;
        sc[si][tj + 12] = a1 * scale;
    }
    __syncthreads();

    // warp-parallel softmax: warp w handles rows w, w+8, w+16
    for (int r = w; r < S; r += 8) {
        float v = (lane < S) ? sc[r][lane] : -1e30f;
        float mx = v;
#pragma unroll
        for (int o = 16; o; o >>= 1) mx = fmaxf(mx, __shfl_xor_sync(0xFFFFFFFFu, mx, o));
        float e = (lane < S) ? expf(v - mx) : 0.f;
        float sum = e;
#pragma unroll
        for (int o = 16; o; o >>= 1) sum += __shfl_xor_sync(0xFFFFFFFFu, sum, o);
        if (lane < S) sc[r][lane] = e * (1.f / sum);
    }
    __syncthreads();

    // AV + residual, float4-blocked (row-contiguous, conflict-free)
    for (int p = tid; p < S * (DH / 4); p += 256) {    // 384 items
        int s = p >> 4, d4 = (p & 15) * 4;
        float4 o = make_float4(0.f, 0.f, 0.f, 0.f);
#pragma unroll
        for (int t = 0; t < S; t++) {
            float wgt = sc[s][t];
            float4 v = *reinterpret_cast<const float4*>(&vs[t][d4]);
            o.x = fmaf(wgt, v.x, o.x);
            o.y = fmaf(wgt, v.y, o.y);
            o.z = fmaf(wgt, v.z, o.z);
            o.w = fmaf(wgt, v.w, o.w);
        }
        size_t xi = (size_t)(s * Bn + b) * Dm + h * DH + d4;
        float4 xv = *reinterpret_cast<const float4*>(g_x + xi);
        xv.x += o.x; xv.y += o.y; xv.z += o.z; xv.w += o.w;
        *reinterpret_cast<float4*>(g_x + xi) = xv;
        *reinterpret_cast<__half2*>(g_xh16 + xi)     = __floats2half2_rn(xv.x, xv.y);
        *reinterpret_cast<__half2*>(g_xh16 + xi + 2) = __floats2half2_rn(xv.z, xv.w);
    }
}

// ---------------------------------------------------------------------------
extern "C" void kernel_launch(void* const* d_in, const int* in_sizes, int n_in,
                              void* d_out, int out_size) {
    const int*   inputs = (const int*)d_in[0];
    // d_in[1] = mask (reference drops it)
    const float* tok = (const float*)d_in[2];
    const float* pe  = (const float*)d_in[3];
    const float* qw  = (const float*)d_in[4];
    const float* qb  = (const float*)d_in[5];
    const float* kw  = (const float*)d_in[6];
    const float* kb  = (const float*)d_in[7];
    const float* vw  = (const float*)d_in[8];
    const float* vb  = (const float*)d_in[9];
    const float* ow  = (const float*)d_in[10];
    const float* ob  = (const float*)d_in[11];
    float* out = (float*)d_out;

    cudaFuncSetAttribute(gemm_qkv_tc, cudaFuncAttributeMaxDynamicSharedMemorySize, SMEM_BYTES);
    cudaFuncSetAttribute(gemm_out_tc, cudaFuncAttributeMaxDynamicSharedMemorySize, SMEM_BYTES);

    conv_wqkv16<<<WROWS, 256>>>(qw, kw, vw);
    conv_wout16<<<Vn, 256>>>(ow);
    embed_kernel<<<Mr, 256>>>(inputs, tok, pe);

    for (int l = 0; l < Ln; l++) {
        gemm_qkv_tc<<<dim3(48, 24), 256, SMEM_BYTES>>>(l, qb, kb, vb);
        attn_kernel<<<Bn * 16, 256>>>();
    }
    gemm_out_tc<<<dim3(48, 250), 256, SMEM_BYTES>>>(ob, out);
}

// round 13
// speedup vs baseline: 1.1478x; 1.1093x over previous
#include <cuda_runtime.h>
#include <cuda_fp16.h>
#include <cstdint>

constexpr int S  = 24;
constexpr int Bn = 256;
constexpr int Dm = 1024;
constexpr int Ln = 12;
constexpr int Vn = 32000;
constexpr int Mr = S * Bn;          // 6144
constexpr int WROWS = Ln * 3 * Dm;  // 36864

// logits GEMM (proven 128x128 core)
constexpr int BM = 128, BN = 128, BK = 64, STAGES = 3;
constexpr int STAGE_BYTES = (BM * BK + BN * BK) * 2;      // 32 KB
constexpr int SMEM_BYTES  = STAGES * STAGE_BYTES;         // 96 KB

// fused layer kernel: 96x192 tile
constexpr int FST_BYTES = (96 * 64 + 192 * 64) * 2;       // 36864
constexpr int FSMEM = 3 * FST_BYTES;                      // 110592
constexpr int LQ = 68;                                    // q/k/v smem row stride

// ---------------- scratch (device globals; no allocation) ----------------
// x rows are [b][s]: row = b*24 + s
__device__ float g_x[(size_t)Mr * Dm];
__device__ uint16_t g_xh16a[(size_t)Mr * Dm];  // fp16 x ping
__device__ uint16_t g_xh16b[(size_t)Mr * Dm];  // fp16 x pong
__device__ uint16_t g_w16[(size_t)WROWS * Dm]; // [l][h][q64|k64|v64][1024]
__device__ uint16_t g_ow16[(size_t)Vn * Dm];   // fp16 out_w

__device__ __forceinline__ uint32_t smem_u32(const void* p) {
    uint32_t a;
    asm("{ .reg .u64 t; cvta.to.shared.u64 t, %1; cvt.u32.u64 %0, t; }" : "=r"(a) : "l"(p));
    return a;
}

// xor swizzle for 128-byte rows: 16B chunk index xored with row%8
__device__ __forceinline__ uint32_t swz(int row, int g) {
    return (uint32_t)(row * 128 + ((g ^ (row & 7)) << 4));
}

// ---------------------------------------------------------------------------
// Fused layer kernel: grid (64 mT, 16 h), 256 threads (8 warps: 2m x 4n).
//   GEMM:  [96 rows of x] . [q|k|v weight slice of head h]^T -> 96x192
//   then in-block attention for 4 batches + residual + fp16 convert.
// ---------------------------------------------------------------------------
__global__ void __launch_bounds__(256, 2) layer_fused(
    int parity,
    const float* __restrict__ qbL, const float* __restrict__ kbL,
    const float* __restrict__ vbL)
{
    extern __shared__ char smem[];
    const uint32_t sb = smem_u32(smem);
    const int tid = threadIdx.x;
    const int lane = tid & 31;
    const int wid = tid >> 5;
    const int wm = wid & 1;          // 2 m-warps: 48 rows each
    const int wn = wid >> 1;         // 4 n-warps: 48 cols each
    const int mT = blockIdx.x;       // 64 tiles of 96 rows
    const int h  = blockIdx.y;

    const uint16_t* Xin = parity ? g_xh16b : g_xh16a;
    uint16_t* Xout      = parity ? g_xh16a : g_xh16b;
    const uint16_t* A = Xin + (size_t)mT * 96 * Dm;
    const uint16_t* W = g_w16 + ((size_t)blockIdx.y + (size_t)parity * 0) * 0
                        + ((size_t)(/*layer*/ 0)) * 0;   // placeholder, set below
    // real W base: [l][h][192][1024]; layer passed via qbL offset trick not used:
    // we pass layer through gridDim-independent param below instead.
    (void)W;
    // NOTE: layer index is folded into qbL/kbL/vbL (pre-offset) and wBase:
    // wBase passed via constant computation from qbL is impossible; use param.
    // -- see kernel argument `lw` below.
    return;  // (never compiled; real kernel is layer_fused2)
}

// Real fused kernel (clean signature: weight base row precomputed on host side)
__global__ void __launch_bounds__(256, 2) layer_fused2(
    int parity, int layer,
    const float* __restrict__ qb, const float* __restrict__ kb,
    const float* __restrict__ vb)
{
    extern __shared__ char smem[];
    const uint32_t sb = smem_u32(smem);
    const int tid = threadIdx.x;
    const int lane = tid & 31;
    const int wid = tid >> 5;
    const int wm = wid & 1;
    const int wn = wid >> 1;
    const int mT = blockIdx.x;
    const int h  = blockIdx.y;

    const uint16_t* Xin = parity ? g_xh16b : g_xh16a;
    uint16_t* Xout      = parity ? g_xh16a : g_xh16b;
    const uint16_t* A = Xin + (size_t)mT * 96 * Dm;
    const uint16_t* W = g_w16 + ((size_t)layer * 16 + h) * 192 * Dm;

    auto loadStage = [&](int it, int slot) {
        const int k0 = it * 64;
        const uint32_t sa = sb + slot * FST_BYTES;
        const uint32_t sw = sa + 96 * 64 * 2;
#pragma unroll
        for (int i = 0; i < 3; i++) {              // A: 768 16B chunks
            int ch = tid + i * 256;
            int r = ch >> 3, cb = ch & 7;
            const void* gp = A + (size_t)r * Dm + k0 + cb * 8;
            asm volatile("cp.async.cg.shared.global [%0], [%1], 16;"
                         :: "r"(sa + swz(r, cb)), "l"(gp));
        }
#pragma unroll
        for (int i = 0; i < 6; i++) {              // W: 1536 16B chunks
            int ch = tid + i * 256;
            int r = ch >> 3, cb = ch & 7;
            const void* gp = W + (size_t)r * Dm + k0 + cb * 8;
            asm volatile("cp.async.cg.shared.global [%0], [%1], 16;"
                         :: "r"(sw + swz(r, cb)), "l"(gp));
        }
        asm volatile("cp.async.commit_group;");
    };

    float acc[3][6][4];
#pragma unroll
    for (int a = 0; a < 3; a++)
#pragma unroll
        for (int b = 0; b < 6; b++)
#pragma unroll
            for (int c = 0; c < 4; c++) acc[a][b][c] = 0.f;

    loadStage(0, 0);
    loadStage(1, 1);

    for (int it = 0; it < 16; it++) {
        if (it + 2 < 16) asm volatile("cp.async.wait_group 1;");
        else             asm volatile("cp.async.wait_group 0;");
        __syncthreads();
        if (it + 2 < 16) loadStage(it + 2, (it + 2) % 3);

        const uint32_t sa = sb + (it % 3) * FST_BYTES;
        const uint32_t sw = sa + 96 * 64 * 2;
#pragma unroll
        for (int q = 0; q < 4; q++) {
            uint32_t afr[3][4], bfr[6][2];
#pragma unroll
            for (int mi = 0; mi < 3; mi++) {
                int m = wm * 48 + mi * 16 + (lane & 15);
                int g = 2 * q + (lane >> 4);
                asm volatile("ldmatrix.sync.aligned.m8n8.x4.shared.b16 {%0,%1,%2,%3}, [%4];"
                             : "=r"(afr[mi][0]), "=r"(afr[mi][1]),
                               "=r"(afr[mi][2]), "=r"(afr[mi][3])
                             : "r"(sa + swz(m, g)));
            }
#pragma unroll
            for (int njp = 0; njp < 3; njp++) {
                int n = wn * 48 + njp * 16 + (lane & 7) + ((lane & 16) >> 1);
                int g = 2 * q + ((lane >> 3) & 1);
                asm volatile("ldmatrix.sync.aligned.m8n8.x4.shared.b16 {%0,%1,%2,%3}, [%4];"
                             : "=r"(bfr[2 * njp][0]), "=r"(bfr[2 * njp][1]),
                               "=r"(bfr[2 * njp + 1][0]), "=r"(bfr[2 * njp + 1][1])
                             : "r"(sw + swz(n, g)));
            }
#pragma unroll
            for (int mi = 0; mi < 3; mi++)
#pragma unroll
                for (int nj = 0; nj < 6; nj++) {
                    asm volatile(
                        "mma.sync.aligned.m16n8k16.row.col.f32.f16.f16.f32 "
                        "{%0,%1,%2,%3}, {%4,%5,%6,%7}, {%8,%9}, {%0,%1,%2,%3};"
                        : "+f"(acc[mi][nj][0]), "+f"(acc[mi][nj][1]),
                          "+f"(acc[mi][nj][2]), "+f"(acc[mi][nj][3])
                        : "r"(afr[mi][0]), "r"(afr[mi][1]),
                          "r"(afr[mi][2]), "r"(afr[mi][3]),
                          "r"(bfr[nj][0]), "r"(bfr[nj][1]));
                }
        }
    }
    __syncthreads();   // all warps done with stage smem; reuse it below

    // ---- scatter q/k/v (+bias) to smem, fp32 ----
    float* Qs = reinterpret_cast<float*>(smem);          // [96][LQ]
    float* Ks = Qs + 96 * LQ;
    float* Vs = Ks + 96 * LQ;
    float* sc = Vs + 96 * LQ;                            // [4][24][24]

    const int rl = lane >> 2;
    const int cl = 2 * (lane & 3);
#pragma unroll
    for (int mi = 0; mi < 3; mi++)
#pragma unroll
        for (int ro = 0; ro < 2; ro++) {
            int row = wm * 48 + mi * 16 + ro * 8 + rl;
#pragma unroll
            for (int nj = 0; nj < 6; nj++) {
                int c = wn * 48 + nj * 8 + cl;
                int mat = c >> 6;
                int cc = c & 63;
                const float* bp = (mat == 0) ? qb : (mat == 1) ? kb : vb;
                float* dst = ((mat == 0) ? Qs : (mat == 1) ? Ks : Vs) + row * LQ + cc;
                dst[0] = acc[mi][nj][ro * 2 + 0] + bp[h * 64 + cc];
                dst[1] = acc[mi][nj][ro * 2 + 1] + bp[h * 64 + cc + 1];
            }
        }
    __syncthreads();

    // ---- scores: 4 batches x 24 x 24 ----
    constexpr float scale = 0.03125f;   // 1/sqrt(1024)
    for (int p = tid; p < 2304; p += 256) {
        int bb = p / 576;
        int rem = p - bb * 576;
        int si = rem / 24, tj = rem - si * 24;
        const float* qrow = Qs + (bb * 24 + si) * LQ;
        const float* krow = Ks + (bb * 24 + tj) * LQ;
        float a = 0.f;
#pragma unroll
        for (int d4 = 0; d4 < 16; d4++) {
            float4 qv = *reinterpret_cast<const float4*>(qrow + d4 * 4);
            float4 kv = *reinterpret_cast<const float4*>(krow + d4 * 4);
            a = fmaf(qv.x, kv.x, fmaf(qv.y, kv.y, fmaf(qv.z, kv.z, fmaf(qv.w, kv.w, a))));
        }
        sc[p] = a * scale;
    }
    __syncthreads();

    // ---- softmax: 96 rows of 24; warp wid handles rows wid*12..+12 ----
#pragma unroll
    for (int rr = 0; rr < 12; rr++) {
        int r = wid * 12 + rr;
        float v = (lane < S) ? sc[r * 24 + lane] : -1e30f;
        float mx = v;
#pragma unroll
        for (int o = 16; o; o >>= 1) mx = fmaxf(mx, __shfl_xor_sync(0xFFFFFFFFu, mx, o));
        float e = (lane < S) ? expf(v - mx) : 0.f;
        float sum = e;
#pragma unroll
        for (int o = 16; o; o >>= 1) sum += __shfl_xor_sync(0xFFFFFFFFu, sum, o);
        if (lane < S) sc[r * 24 + lane] = e * (1.f / sum);
    }
    __syncthreads();

    // ---- AV + residual + fp16 convert ----
    for (int p = tid; p < 1536; p += 256) {
        int bb = p / 384;
        int rem = p - bb * 384;
        int si = rem >> 4, dg = rem & 15;
        const float* scrow = sc + (bb * 24 + si) * 24;
        float4 o = make_float4(0.f, 0.f, 0.f, 0.f);
#pragma unroll
        for (int t = 0; t < S; t++) {
            float wgt = scrow[t];
            float4 vv = *reinterpret_cast<const float4*>(Vs + (bb * 24 + t) * LQ + dg * 4);
            o.x = fmaf(wgt, vv.x, o.x);
            o.y = fmaf(wgt, vv.y, o.y);
            o.z = fmaf(wgt, vv.z, o.z);
            o.w = fmaf(wgt, vv.w, o.w);
        }
        int rg = (mT * 4 + bb) * 24 + si;
        size_t off = (size_t)rg * Dm + h * 64 + dg * 4;
        float4 xv = *reinterpret_cast<const float4*>(g_x + off);
        xv.x += o.x; xv.y += o.y; xv.z += o.z; xv.w += o.w;
        *reinterpret_cast<float4*>(g_x + off) = xv;
        *reinterpret_cast<__half2*>(Xout + off)     = __floats2half2_rn(xv.x, xv.y);
        *reinterpret_cast<__half2*>(Xout + off + 2) = __floats2half2_rn(xv.z, xv.w);
    }
}

// ---------------------------------------------------------------------------
// Logits GEMM (128x128 proven core; A rows are [b][s], output rows [s][b])
// ---------------------------------------------------------------------------
__global__ void __launch_bounds__(256, 2) gemm_out_tc(
    const float* __restrict__ ob, float* __restrict__ out)
{
    const int mT = blockIdx.x, nT = blockIdx.y;
    const uint16_t* A = g_xh16a + (size_t)mT * 128 * Dm;
    const uint16_t* W = g_ow16 + (size_t)nT * 128 * Dm;
    const float* bias = ob + nT * 128;

    extern __shared__ char smem[];
    const uint32_t sb = smem_u32(smem);
    const int tid = threadIdx.x;
    const int lane = tid & 31;
    const int wid = tid >> 5;
    const int wm = wid & 3;
    const int wn = wid >> 2;

    auto loadStage = [&](int it, int slot) {
        const int k0 = it * BK;
        const uint32_t sa = sb + slot * STAGE_BYTES;
        const uint32_t sw = sa + BM * BK * 2;
#pragma unroll
        for (int i = 0; i < 4; i++) {
            int ch = tid + i * 256;
            int r = ch >> 3, cb = ch & 7;
            const void* gp = A + (size_t)r * Dm + k0 + cb * 8;
            asm volatile("cp.async.cg.shared.global [%0], [%1], 16;"
                         :: "r"(sa + swz(r, cb)), "l"(gp));
        }
#pragma unroll
        for (int i = 0; i < 4; i++) {
            int ch = tid + i * 256;
            int r = ch >> 3, cb = ch & 7;
            const void* gp = W + (size_t)r * Dm + k0 + cb * 8;
            asm volatile("cp.async.cg.shared.global [%0], [%1], 16;"
                         :: "r"(sw + swz(r, cb)), "l"(gp));
        }
        asm volatile("cp.async.commit_group;");
    };

    float acc[2][8][4];
#pragma unroll
    for (int a = 0; a < 2; a++)
#pragma unroll
        for (int b = 0; b < 8; b++)
#pragma unroll
            for (int c = 0; c < 4; c++) acc[a][b][c] = 0.f;

    loadStage(0, 0);
    loadStage(1, 1);

    for (int it = 0; it < 16; it++) {
        if (it + 2 < 16) asm volatile("cp.async.wait_group 1;");
        else             asm volatile("cp.async.wait_group 0;");
        __syncthreads();
        if (it + 2 < 16) loadStage(it + 2, (it + 2) % STAGES);

        const uint32_t sa = sb + (it % STAGES) * STAGE_BYTES;
        const uint32_t sw = sa + BM * BK * 2;
#pragma unroll
        for (int q = 0; q < 4; q++) {
            uint32_t afr[2][4], bfr[8][2];
#pragma unroll
            for (int mi = 0; mi < 2; mi++) {
                int m = wm * 32 + mi * 16 + (lane & 15);
                int g = 2 * q + (lane >> 4);
                asm volatile("ldmatrix.sync.aligned.m8n8.x4.shared.b16 {%0,%1,%2,%3}, [%4];"
                             : "=r"(afr[mi][0]), "=r"(afr[mi][1]),
                               "=r"(afr[mi][2]), "=r"(afr[mi][3])
                             : "r"(sa + swz(m, g)));
            }
#pragma unroll
            for (int nj = 0; nj < 8; nj += 2) {
                int n = wn * 64 + nj * 8 + (lane & 7) + ((lane & 16) >> 1);
                int g = 2 * q + ((lane >> 3) & 1);
                asm volatile("ldmatrix.sync.aligned.m8n8.x4.shared.b16 {%0,%1,%2,%3}, [%4];"
                             : "=r"(bfr[nj][0]), "=r"(bfr[nj][1]),
                               "=r"(bfr[nj + 1][0]), "=r"(bfr[nj + 1][1])
                             : "r"(sw + swz(n, g)));
            }
#pragma unroll
            for (int mi = 0; mi < 2; mi++)
#pragma unroll
                for (int nj = 0; nj < 8; nj++) {
                    asm volatile(
                        "mma.sync.aligned.m16n8k16.row.col.f32.f16.f16.f32 "
                        "{%0,%1,%2,%3}, {%4,%5,%6,%7}, {%8,%9}, {%0,%1,%2,%3};"
                        : "+f"(acc[mi][nj][0]), "+f"(acc[mi][nj][1]),
                          "+f"(acc[mi][nj][2]), "+f"(acc[mi][nj][3])
                        : "r"(afr[mi][0]), "r"(afr[mi][1]),
                          "r"(afr[mi][2]), "r"(afr[mi][3]),
                          "r"(bfr[nj][0]), "r"(bfr[nj][1]));
                }
        }
    }

    const int r0 = wm * 32 + (lane >> 2);
    const int cl = 2 * (lane & 3);
#pragma unroll
    for (int mi = 0; mi < 2; mi++)
#pragma unroll
        for (int ro = 0; ro < 2; ro++) {
            int rg = mT * 128 + r0 + mi * 16 + ro * 8;     // [b][s] row
            int bb = rg / 24, ss = rg - bb * 24;
            float* crow = out + ((size_t)ss * Bn + bb) * Vn;
#pragma unroll
            for (int nj = 0; nj < 8; nj++) {
                int col = wn * 64 + nj * 8 + cl;
                float2 o;
                o.x = acc[mi][nj][ro * 2 + 0] + bias[col];
                o.y = acc[mi][nj][ro * 2 + 1] + bias[col + 1];
                *reinterpret_cast<float2*>(crow + nT * 128 + col) = o;
            }
        }
}

// ---------------------------------------------------------------------------
// Weight prep: qkv -> [l][h][q64|k64|v64][1024] fp16;  out_w -> fp16
// ---------------------------------------------------------------------------
__global__ void conv_wqkv16(const float* __restrict__ qw, const float* __restrict__ kw,
                            const float* __restrict__ vw) {
    size_t t = (size_t)blockIdx.x * 256 + threadIdx.x;
    size_t e = t * 4;
    int row = (int)(e >> 10);        // dest row in [l][h][192]
    int col = (int)(e & 1023);
    int l    = row / 3072;
    int rem  = row - l * 3072;
    int hh   = rem / 192;
    int rem2 = rem - hh * 192;
    int mat  = rem2 >> 6;
    int n    = hh * 64 + (rem2 & 63);
    const float* src = ((mat == 0) ? qw : (mat == 1) ? kw : vw)
                       + (((size_t)l * 1024 + n) << 10) + col;
    float4 v = *reinterpret_cast<const float4*>(src);
    size_t d = ((size_t)row << 10) + col;
    *reinterpret_cast<__half2*>(g_w16 + d)     = __floats2half2_rn(v.x, v.y);
    *reinterpret_cast<__half2*>(g_w16 + d + 2) = __floats2half2_rn(v.z, v.w);
}

__global__ void conv_wout16(const float* __restrict__ ow) {
    size_t e = ((size_t)blockIdx.x * 256 + threadIdx.x) * 4;
    float4 v = *reinterpret_cast<const float4*>(ow + e);
    *reinterpret_cast<__half2*>(g_ow16 + e)     = __floats2half2_rn(v.x, v.y);
    *reinterpret_cast<__half2*>(g_ow16 + e + 2) = __floats2half2_rn(v.z, v.w);
}

// ---------------------------------------------------------------------------
// Embedding into [b][s] layout + fp16 convert (buffer A)
// ---------------------------------------------------------------------------
__global__ void embed_kernel(const int* __restrict__ inputs,
                             const float* __restrict__ tok,
                             const float* __restrict__ pe) {
    int row = blockIdx.x;            // b*24 + s
    int b = row / 24;
    int s = row - b * 24;
    int t = inputs[s * Bn + b];
    const float4* te = reinterpret_cast<const float4*>(tok + (size_t)t * Dm);
    const float4* pp = reinterpret_cast<const float4*>(pe + (size_t)s * Dm);
    float4 a = te[threadIdx.x];
    float4 bp = pp[threadIdx.x];
    float4 o = make_float4(a.x + bp.x, a.y + bp.y, a.z + bp.z, a.w + bp.w);
    size_t d = (size_t)row * Dm + threadIdx.x * 4;
    *reinterpret_cast<float4*>(g_x + d) = o;
    *reinterpret_cast<__half2*>(g_xh16a + d)     = __floats2half2_rn(o.x, o.y);
    *reinterpret_cast<__half2*>(g_xh16a + d + 2) = __floats2half2_rn(o.z, o.w);
}

// ---------------------------------------------------------------------------
extern "C" void kernel_launch(void* const* d_in, const int* in_sizes, int n_in,
                              void* d_out, int out_size) {
    const int*   inputs = (const int*)d_in[0];
    // d_in[1] = mask (reference drops it)
    const float* tok = (const float*)d_in[2];
    const float* pe  = (const float*)d_in[3];
    const float* qw  = (const float*)d_in[4];
    const float* qb  = (const float*)d_in[5];
    const float* kw  = (const float*)d_in[6];
    const float* kb  = (const float*)d_in[7];
    const float* vw  = (const float*)d_in[8];
    const float* vb  = (const float*)d_in[9];
    const float* ow  = (const float*)d_in[10];
    const float* ob  = (const float*)d_in[11];
    float* out = (float*)d_out;

    cudaFuncSetAttribute(layer_fused2, cudaFuncAttributeMaxDynamicSharedMemorySize, FSMEM);
    cudaFuncSetAttribute(gemm_out_tc, cudaFuncAttributeMaxDynamicSharedMemorySize, SMEM_BYTES);

    conv_wqkv16<<<WROWS, 256>>>(qw, kw, vw);
    conv_wout16<<<Vn, 256>>>(ow);
    embed_kernel<<<Mr, 256>>>(inputs, tok, pe);

    for (int l = 0; l < Ln; l++) {
        layer_fused2<<<dim3(64, 16), 256, FSMEM>>>(
            l & 1, l, qb + (size_t)l * Dm, kb + (size_t)l * Dm, vb + (size_t)l * Dm);
    }
    gemm_out_tc<<<dim3(48, 250), 256, SMEM_BYTES>>>(ob, out);
}